// round 16
// baseline (speedup 1.0000x reference)
#include <cuda_runtime.h>
#include <cuda_bf16.h>
#include <cstdint>
#include <math.h>

#define BATCH 8
#define NN 2048
#define FF 256
#define NFEAT 512              // Wh (256) stacked with wl (256)
#define BN (BATCH * NN)        // 16384
#define ALPHA 0.2f

// ---------------- scratch (static device allocations; no cudaMalloc) --------
__device__ __nv_bfloat16 d_att_hi[(size_t)BATCH * NN * NN];  // 67 MB
__device__ __nv_bfloat16 d_att_lo[(size_t)BATCH * NN * NN];  // 67 MB
__device__ __nv_bfloat16 d_bth[(size_t)BATCH * NFEAT * NN];  // 16 MB  [b][feat][node]
__device__ __nv_bfloat16 d_btl[(size_t)BATCH * NFEAT * NN];  // 16 MB
__device__ __nv_bfloat16 d_wth[2 * FF * FF];                 // W1^T|W2^T hi
__device__ __nv_bfloat16 d_wtl[2 * FF * FF];
__device__ float d_s1[BN];
__device__ float d_s2[BN];
__device__ float d_v[2 * FF];

// ---------------- kernel 1: v1 = W1 @ a[:F], v2 = W1 @ a[F:] ----------------
__global__ void v_kernel(const float* __restrict__ W1, const float* __restrict__ a,
                         float* __restrict__ v) {
    int k = threadIdx.x;
    float acc1 = 0.f, acc2 = 0.f;
    const float* wrow = W1 + (size_t)k * FF;
#pragma unroll 8
    for (int c = 0; c < FF; c++) {
        float w = wrow[c];
        acc1 += w * a[c];
        acc2 += w * a[FF + c];
    }
    v[k] = acc1;
    v[FF + k] = acc2;
}

// ------------- split helpers: fp32 -> bf16 hi/lo ----------------------------
__device__ __forceinline__ void split1(float p, __nv_bfloat16& hi, __nv_bfloat16& lo) {
    hi = __float2bfloat16(p);
    lo = __float2bfloat16(p - __bfloat162float(hi));
}

__global__ void split_w(const float* __restrict__ W1, const float* __restrict__ W2,
                        __nv_bfloat16* __restrict__ wth, __nv_bfloat16* __restrict__ wtl) {
    int z = blockIdx.y;
    int n = blockIdx.x;
    int k = threadIdx.x;
    const float* W = z ? W2 : W1;
    float p = W[(size_t)k * FF + n];     // transpose: Wt[n][k] = W[k][n]
    size_t o = (size_t)z * FF * FF + (size_t)n * FF + k;
    __nv_bfloat16 hi, lo;
    split1(p, hi, lo);
    wth[o] = hi;
    wtl[o] = lo;
}

// ------- kernel 3: s1 = h.v1, s2 = h.v2 (exact fp32, warp per row) ----------
__global__ void scores_kernel(const float* __restrict__ h, const float* __restrict__ v,
                              float* __restrict__ s1, float* __restrict__ s2) {
    int w = threadIdx.x >> 5, lane = threadIdx.x & 31;
    int r = blockIdx.x * 8 + w;
    const float4* hr = (const float4*)(h + (size_t)r * FF);
    const float4* v1p = (const float4*)v;
    const float4* v2p = (const float4*)(v + FF);
    float a1 = 0.f, a2 = 0.f;
#pragma unroll
    for (int i = 0; i < 2; i++) {
        int c4 = lane + i * 32;
        float4 hv = hr[c4];
        float4 x1 = v1p[c4];
        float4 x2 = v2p[c4];
        a1 += hv.x * x1.x + hv.y * x1.y + hv.z * x1.z + hv.w * x1.w;
        a2 += hv.x * x2.x + hv.y * x2.y + hv.z * x2.z + hv.w * x2.w;
    }
#pragma unroll
    for (int o = 16; o; o >>= 1) {
        a1 += __shfl_xor_sync(0xffffffffu, a1, o);
        a2 += __shfl_xor_sync(0xffffffffu, a2, o);
    }
    if (lane == 0) { s1[r] = a1; s2[r] = a2; }
}

// --- kernel 4: masked leaky-relu softmax (register-resident) -> bf16 hi/lo --
__global__ void softmax_kernel(const int* __restrict__ adj, const float* __restrict__ s1,
                               const float* __restrict__ s2,
                               __nv_bfloat16* __restrict__ att_hi,
                               __nv_bfloat16* __restrict__ att_lo) {
    int bi = blockIdx.x;
    int b = bi >> 11;
    const int4* arow = (const int4*)(adj + (size_t)bi * NN);
    const float4* s2b = (const float4*)(s2 + (size_t)b * NN);
    float si = s1[bi];

    __shared__ float redm[8];
    __shared__ float reds[8];
    int tid = threadIdx.x;
    int lane = tid & 31, warp = tid >> 5;

    float r[8];
    float lmax = -3.4e38f;
#pragma unroll
    for (int c = 0; c < 2; c++) {
        int j4 = tid + c * 256;
        int4 av = arow[j4];
        float4 sv = s2b[j4];
        float v0 = si + sv.x; v0 = v0 > 0.f ? v0 : ALPHA * v0; v0 = av.x > 0 ? v0 : -9.0e15f;
        float v1 = si + sv.y; v1 = v1 > 0.f ? v1 : ALPHA * v1; v1 = av.y > 0 ? v1 : -9.0e15f;
        float v2 = si + sv.z; v2 = v2 > 0.f ? v2 : ALPHA * v2; v2 = av.z > 0 ? v2 : -9.0e15f;
        float v3 = si + sv.w; v3 = v3 > 0.f ? v3 : ALPHA * v3; v3 = av.w > 0 ? v3 : -9.0e15f;
        r[c * 4 + 0] = v0; r[c * 4 + 1] = v1; r[c * 4 + 2] = v2; r[c * 4 + 3] = v3;
        lmax = fmaxf(fmaxf(fmaxf(lmax, v0), fmaxf(v1, v2)), v3);
    }
#pragma unroll
    for (int o = 16; o; o >>= 1) lmax = fmaxf(lmax, __shfl_xor_sync(0xffffffffu, lmax, o));
    if (lane == 0) redm[warp] = lmax;
    __syncthreads();
    float m = redm[0];
#pragma unroll
    for (int w = 1; w < 8; w++) m = fmaxf(m, redm[w]);

    float lsum = 0.f;
#pragma unroll
    for (int q = 0; q < 8; q++) {
        float e = __expf(r[q] - m);
        r[q] = e;
        lsum += e;
    }
#pragma unroll
    for (int o = 16; o; o >>= 1) lsum += __shfl_xor_sync(0xffffffffu, lsum, o);
    if (lane == 0) reds[warp] = lsum;
    __syncthreads();
    float tot = 0.f;
#pragma unroll
    for (int w = 0; w < 8; w++) tot += reds[w];
    float inv = 1.f / tot;

    uint2* oh = (uint2*)(att_hi + (size_t)bi * NN);
    uint2* ol = (uint2*)(att_lo + (size_t)bi * NN);
#pragma unroll
    for (int c = 0; c < 2; c++) {
        int j4 = tid + c * 256;
        union { __nv_bfloat16 h[4]; uint2 u; } H, L;
#pragma unroll
        for (int q = 0; q < 4; q++) {
            float p = r[c * 4 + q] * inv;
            H.h[q] = __float2bfloat16(p);
            L.h[q] = __float2bfloat16(p - __bfloat162float(H.h[q]));
        }
        oh[j4] = H.u;
        ol[j4] = L.u;
    }
}

// ======================= shared helpers =====================================
__device__ __forceinline__ uint32_t smem_u32(const void* p) {
    uint32_t a;
    asm("{ .reg .u64 t; cvta.to.shared.u64 t, %1; cvt.u32.u64 %0, t; }"
        : "=r"(a) : "l"(p));
    return a;
}
__device__ __forceinline__ float elu_f(float v) {
    return v > 0.f ? v : (__expf(v) - 1.f);
}

#define OFF_TMEM 0
#define OFF_MBAR 8
#define OFF_BUF  1024
// feat_mma: 4 stages x 48KB (K-tile 32)
#define F_STAGE_BYTES 49152
#define F_NSTAGE 4
// attn_mma: 3 stages x 64KB (M=256: Ahi 16K | Alo 16K | Bhi 16K | Blo 16K)
#define A_STAGE_BYTES 65536
#define A_NSTAGE 3
#define MMA_SMEM_BYTES (OFF_BUF + 3 * A_STAGE_BYTES)      // 197632 (covers both)
#define CT_PAD 264                     // floats; 264*4=1056 bytes, 16B-aligned rows

#if defined(__CUDA_ARCH__) && (defined(__CUDA_ARCH_FEAT_SM103_ALL) || defined(__CUDA_ARCH_FEAT_SM100_ALL) || defined(__CUDA_ARCH_FEAT_SM101_ALL))
#define HAS_TCGEN05 1
#else
#define HAS_TCGEN05 0
#endif

#if HAS_TCGEN05
// ================= tcgen05 helpers (sm_103a SASS) ===========================
__device__ __forceinline__ uint32_t elect_one_pred() {
    uint32_t pred;
    asm volatile(
        "{\n\t.reg .pred p;\n\telect.sync _|p, 0xFFFFFFFF;\n\t"
        "selp.b32 %0, 1, 0, p;\n\t}" : "=r"(pred));
    return pred;
}
#define MBARRIER_INIT(addr, cnt) \
    asm volatile("mbarrier.init.shared.b64 [%0], %1;" :: "r"((uint32_t)(addr)), "r"((uint32_t)(cnt)) : "memory")
#define MBARRIER_INVAL(addr) \
    asm volatile("mbarrier.inval.shared.b64 [%0];" :: "r"((uint32_t)(addr)) : "memory")
#define MBARRIER_WAIT_PARITY(mbar_smem_addr, phase_parity) do { \
    uint32_t _mbar = (uint32_t)(mbar_smem_addr); \
    uint32_t _parity = (uint32_t)(phase_parity); \
    uint32_t _done; \
    asm volatile( \
        "{\n\t.reg .pred p;\n\t" \
        "mbarrier.try_wait.parity.acquire.cta.shared::cta.b64 p, [%1], %2;\n\t" \
        "selp.b32 %0, 1, 0, p;\n\t}" \
        : "=r"(_done) : "r"(_mbar), "r"(_parity) : "memory"); \
    if (!_done) { \
        asm volatile( \
            "{\n\t.reg .pred P1;\n\t" \
            "WAIT_LOOP_%=:\n\t" \
            "mbarrier.try_wait.parity.acquire.cta.shared::cta.b64 P1, [%0], %1, 0x989680;\n\t" \
            "@P1 bra.uni WAIT_DONE_%=;\n\t" \
            "bra.uni WAIT_LOOP_%=;\n\t" \
            "WAIT_DONE_%=:\n\t}" \
            :: "r"(_mbar), "r"(_parity) : "memory"); \
    } \
} while (0)
#define TCGEN05_ALLOC(saddr, n) \
    asm volatile("tcgen05.alloc.cta_group::1.sync.aligned.shared::cta.b32 [%0], %1;" \
                 :: "r"((uint32_t)(saddr)), "r"((uint32_t)(n)) : "memory")
#define TCGEN05_DEALLOC(tm, n) \
    asm volatile("tcgen05.dealloc.cta_group::1.sync.aligned.b32 %0, %1;" :: "r"(tm), "r"((uint32_t)(n)))
#define TCGEN05_RELINQUISH() \
    asm volatile("tcgen05.relinquish_alloc_permit.cta_group::1.sync.aligned;")
#define TCGEN05_COMMIT(mbar) \
    asm volatile("tcgen05.commit.cta_group::1.mbarrier::arrive::one.shared::cluster.b64 [%0];" \
                 :: "r"((uint32_t)(mbar)) : "memory")
#define TCGEN05_FENCE_AFTER() asm volatile("tcgen05.fence::after_thread_sync;" ::: "memory")
#define TCGEN05_FENCE_BEFORE() asm volatile("tcgen05.fence::before_thread_sync;" ::: "memory")
#define TCGEN05_WAIT_LD() asm volatile("tcgen05.wait::ld.sync.aligned;" ::: "memory")
#define FENCE_PROXY_ASYNC() asm volatile("fence.proxy.async.shared::cta;" ::: "memory")
#define CP_ASYNC16(dst, src) \
    asm volatile("cp.async.cg.shared.global [%0], [%1], 16;" :: "r"((uint32_t)(dst)), "l"(src) : "memory")
#define CP_COMMIT() asm volatile("cp.async.commit_group;" ::: "memory")
#define CP_WAIT(n)  asm volatile("cp.async.wait_group %0;" :: "n"(n) : "memory")
#define TCGEN05_LD_32X32B_X32(r, tmem_addr) \
    asm volatile( \
        "tcgen05.ld.sync.aligned.32x32b.x32.b32 " \
        "{%0, %1, %2, %3, %4, %5, %6, %7, " \
        " %8, %9, %10, %11, %12, %13, %14, %15, " \
        " %16, %17, %18, %19, %20, %21, %22, %23, " \
        " %24, %25, %26, %27, %28, %29, %30, %31}, [%32];" \
        : "=r"((r)[0]),  "=r"((r)[1]),  "=r"((r)[2]),  "=r"((r)[3]), \
          "=r"((r)[4]),  "=r"((r)[5]),  "=r"((r)[6]),  "=r"((r)[7]), \
          "=r"((r)[8]),  "=r"((r)[9]),  "=r"((r)[10]), "=r"((r)[11]), \
          "=r"((r)[12]), "=r"((r)[13]), "=r"((r)[14]), "=r"((r)[15]), \
          "=r"((r)[16]), "=r"((r)[17]), "=r"((r)[18]), "=r"((r)[19]), \
          "=r"((r)[20]), "=r"((r)[21]), "=r"((r)[22]), "=r"((r)[23]), \
          "=r"((r)[24]), "=r"((r)[25]), "=r"((r)[26]), "=r"((r)[27]), \
          "=r"((r)[28]), "=r"((r)[29]), "=r"((r)[30]), "=r"((r)[31]) \
        : "r"(tmem_addr))

// SW64 K-major descriptor: layout=4, version=1, SBO=32 (512B = 8 rows x 64B), LBO=1
static constexpr uint64_t SMEM_DESC_BASE_SW64 =
    (uint64_t(4) << 61) | (uint64_t(1) << 46) | (uint64_t(32) << 32) | (uint64_t(1) << 16);
#define MAKE_DESC64(base_addr) \
    (SMEM_DESC_BASE_SW64 | ((uint64_t)((base_addr) >> 4) & 0x3FFF))
#define SMEM_SWZ64(o) ((o) ^ (((o) >> 3) & 0x30))

__device__ __forceinline__ void mma_bf16_ss(uint32_t d_tmem, uint64_t a_desc,
                                            uint64_t b_desc, uint32_t idesc, uint32_t en) {
    asm volatile(
        "{\n\t.reg .pred p;\n\tsetp.ne.u32 p, %4, 0;\n\t"
        "tcgen05.mma.cta_group::1.kind::f16 [%0], %1, %2, %3, {%5, %5, %5, %5}, p;\n\t}"
        :: "r"(d_tmem), "l"(a_desc), "l"(b_desc), "r"(idesc), "r"(en), "r"(0u)
        : "memory");
}
// idesc: f32 accum, bf16 a/b, N=256, M=128
static constexpr uint32_t MMA_IDESC =
    (1u << 4) | (1u << 7) | (1u << 10) | ((256u / 8) << 17) | ((128u / 16) << 24);
#endif  // HAS_TCGEN05

// ============ kernel 2: feat_mma: BT[hi/lo] = split((x @ W)^T) ==============
// M=128 nodes, N=256 feats, K=256; 4-stage K32. A fp32->bf16 split in-kernel.
__global__ void __launch_bounds__(256, 1)
feat_mma(const float* __restrict__ xh_f32 /*h*/, const float* __restrict__ lr_f32,
         const __nv_bfloat16* __restrict__ wth, const __nv_bfloat16* __restrict__ wtl,
         __nv_bfloat16* __restrict__ BTh, __nv_bfloat16* __restrict__ BTl) {
    extern __shared__ char smem[];
    const int tid = threadIdx.x;
    const int wid = tid >> 5;
    const int lid = tid & 31;
    const int m0 = blockIdx.x * 128;
    const int z = blockIdx.y;
    const float* A = (z ? lr_f32 : xh_f32) + (size_t)m0 * FF;
    const __nv_bfloat16* Bh = wth + (size_t)z * FF * FF;
    const __nv_bfloat16* Bl = wtl + (size_t)z * FF * FF;
    const int b = m0 >> 11;
    const int node0 = m0 & (NN - 1);

#if HAS_TCGEN05
    uint32_t sbase = smem_u32(smem);
    if (wid == 0) TCGEN05_ALLOC(sbase + OFF_TMEM, 256);
    if (tid == 0) {
        for (int i = 0; i < F_NSTAGE; i++) MBARRIER_INIT(sbase + OFF_MBAR + i * 8, 1);
    }
    __syncthreads();
    uint32_t tmem;
    asm volatile("ld.shared.b32 %0, [%1];" : "=r"(tmem) : "r"(sbase + OFF_TMEM));

    const int arow0 = tid >> 2;
    const int akc = (tid & 3) * 8;

    auto lda = [&](int it, float4* rg) {
        int k0 = it * 32;
#pragma unroll
        for (int i = 0; i < 2; i++) {
            int row = arow0 + i * 64;
            const float* p = A + (size_t)row * FF + k0 + akc;
            rg[i * 2 + 0] = *(const float4*)p;
            rg[i * 2 + 1] = *(const float4*)(p + 4);
        }
    };
    auto sta = [&](int it, const float4* rg) {
        int s = it & (F_NSTAGE - 1);
        char* sb = smem + OFF_BUF + s * F_STAGE_BYTES;
#pragma unroll
        for (int i = 0; i < 2; i++) {
            int row = arow0 + i * 64;
            uint32_t doff = SMEM_SWZ64((uint32_t)(row * 64 + akc * 2));
            union { __nv_bfloat16 h[8]; uint4 u; } H, L;
            const float* f = (const float*)&rg[i * 2];
#pragma unroll
            for (int q = 0; q < 8; q++) split1(f[q], H.h[q], L.h[q]);
            *(uint4*)(sb + doff) = H.u;
            *(uint4*)(sb + 8192 + doff) = L.u;
        }
    };
    auto ldb = [&](int it) {
        int s = it & (F_NSTAGE - 1);
        int k0 = it * 32;
        uint32_t sb = sbase + OFF_BUF + s * F_STAGE_BYTES;
#pragma unroll
        for (int i = 0; i < 4; i++) {
            int idx = tid + i * 256;
            int row = idx >> 2;
            int kc = (idx & 3) * 8;
            uint32_t doff = SMEM_SWZ64((uint32_t)(row * 64 + kc * 2));
            CP_ASYNC16(sb + 16384 + doff, Bh + (size_t)row * FF + k0 + kc);
            CP_ASYNC16(sb + 32768 + doff, Bl + (size_t)row * FF + k0 + kc);
        }
    };

    const int NIT = FF / 32;   // 8
    {
        float4 r0[4], r1[4], r2[4];
        lda(0, r0); lda(1, r1); lda(2, r2);
        sta(0, r0); ldb(0); CP_COMMIT();
        sta(1, r1); ldb(1); CP_COMMIT();
        sta(2, r2); ldb(2); CP_COMMIT();
    }

    float4 rg[4];
    int ph[F_NSTAGE] = {0, 0, 0, 0};
    for (int it = 0; it < NIT; it++) {
        int s = it & (F_NSTAGE - 1);
        if (it + 3 < NIT) lda(it + 3, rg);
        CP_WAIT(2);
        // slot-free wait for stage it+3 (prior user: MMA batch it-1):
        // single elected thread waits; __syncthreads propagates to all.
        if (it >= 1 && it + 3 < NIT) {
            int so = (it - 1) & (F_NSTAGE - 1);
            if (wid == 0) {
                if (elect_one_pred()) {
                    MBARRIER_WAIT_PARITY(sbase + OFF_MBAR + so * 8, ph[so]);
                }
            }
            ph[so] ^= 1;   // all threads keep parity in sync
        }
        __syncthreads();
        if (wid == 0) {
            if (elect_one_pred()) {
                FENCE_PROXY_ASYNC();
                uint32_t sb = sbase + OFF_BUF + s * F_STAGE_BYTES;
                uint64_t dA[2] = { MAKE_DESC64(sb),         MAKE_DESC64(sb + 8192) };
                uint64_t dB[2] = { MAKE_DESC64(sb + 16384), MAKE_DESC64(sb + 32768) };
#pragma unroll
                for (int p = 0; p < 3; p++) {
                    int ai = (p == 2) ? 1 : 0;
                    int bi2 = (p == 1) ? 1 : 0;
#pragma unroll
                    for (int ks = 0; ks < 2; ks++) {
                        uint32_t en = !(it == 0 && p == 0 && ks == 0);
                        mma_bf16_ss(tmem, dA[ai] + ks * 2, dB[bi2] + ks * 2, MMA_IDESC, en);
                    }
                }
                TCGEN05_COMMIT(sbase + OFF_MBAR + s * 8);
            }
        }
        if (it + 3 < NIT) {
            sta(it + 3, rg);
            ldb(it + 3);
        }
        CP_COMMIT();
    }
    {
        int sl = (NIT - 1) & (F_NSTAGE - 1);
        MBARRIER_WAIT_PARITY(sbase + OFF_MBAR + sl * 8, ph[sl]);
    }
    CP_WAIT(0);
    TCGEN05_FENCE_AFTER();
    __syncthreads();

    float* Ct = (float*)(smem + OFF_BUF);      // [256][128]
    {
        int sp = wid & 3;
        int half = wid >> 2;
        int node = sp * 32 + lid;
#pragma unroll
        for (int c2 = 0; c2 < 4; c2++) {
            uint32_t dr[32];
            TCGEN05_LD_32X32B_X32(dr, tmem + half * 128 + c2 * 32);
            TCGEN05_WAIT_LD();
            int f0 = half * 128 + c2 * 32;
#pragma unroll
            for (int c = 0; c < 32; c++)
                Ct[(f0 + c) * 128 + node] = __uint_as_float(dr[c]);
        }
        TCGEN05_FENCE_BEFORE();
    }
    __syncthreads();
    {
#pragma unroll 4
        for (int j = 0; j < 32; j++) {
            int f = wid * 32 + j;
            float4 vv = *(const float4*)(Ct + f * 128 + lid * 4);
            union { __nv_bfloat16 h[4]; uint2 u; } H, L;
            split1(vv.x, H.h[0], L.h[0]);
            split1(vv.y, H.h[1], L.h[1]);
            split1(vv.z, H.h[2], L.h[2]);
            split1(vv.w, H.h[3], L.h[3]);
            size_t rowbase = ((size_t)b * NFEAT + z * 256 + f) * NN + node0 + lid * 4;
            *(uint2*)(BTh + rowbase) = H.u;
            *(uint2*)(BTl + rowbase) = L.u;
        }
    }
    __syncthreads();
    if (tid == 0) {
        for (int i = 0; i < F_NSTAGE; i++) MBARRIER_INVAL(sbase + OFF_MBAR + i * 8);
    }
    __syncthreads();
    if (wid == 0) {
        TCGEN05_RELINQUISH();
        TCGEN05_DEALLOC(tmem, 256);
    }
#else
    for (int e = tid; e < 128 * 256; e += 256) {
        int mi = e >> 8, nj = e & 255;
        float acc = 0.f;
        for (int k = 0; k < FF; k++) {
            float av = A[(size_t)mi * FF + k];
            float bv = __bfloat162float(Bh[(size_t)nj * FF + k]) +
                       __bfloat162float(Bl[(size_t)nj * FF + k]);
            acc += av * bv;
        }
        __nv_bfloat16 hi, lo;
        split1(acc, hi, lo);
        size_t o = ((size_t)b * NFEAT + z * 256 + nj) * NN + node0 + mi;
        BTh[o] = hi;
        BTl[o] = lo;
    }
#endif
}

// ============== kernel 5: attn_mma: out = elu(att @ [Wh|wl]) ================
// M=256 per CTA (two 128-row TMEM accumulators sharing one B tile), N=256.
// K=2048 in 64 tiles of 32; 3-stage x 64KB synchronous pipeline.
__global__ void __launch_bounds__(256, 1)
attn_mma(const __nv_bfloat16* __restrict__ att_hi, const __nv_bfloat16* __restrict__ att_lo,
         const __nv_bfloat16* __restrict__ BTh, const __nv_bfloat16* __restrict__ BTl,
         float* __restrict__ out) {
    extern __shared__ char smem[];
    const int tid = threadIdx.x;
    const int wid = tid >> 5;
    const int lid = tid & 31;
    const int b = blockIdx.z;
    const int m0 = blockIdx.x * 256;
    const int n0g = blockIdx.y * 256;     // 0 -> out1, 256 -> out2
    const __nv_bfloat16* Ah = att_hi + (size_t)b * NN * NN;
    const __nv_bfloat16* Al = att_lo + (size_t)b * NN * NN;
    const __nv_bfloat16* Bh = BTh + (size_t)b * NFEAT * NN + (size_t)n0g * NN;
    const __nv_bfloat16* Bl = BTl + (size_t)b * NFEAT * NN + (size_t)n0g * NN;

#if HAS_TCGEN05
    uint32_t sbase = smem_u32(smem);
    if (wid == 0) TCGEN05_ALLOC(sbase + OFF_TMEM, 512);
    if (tid == 0) {
        for (int i = 0; i < A_NSTAGE; i++) MBARRIER_INIT(sbase + OFF_MBAR + i * 8, 1);
    }
    __syncthreads();
    uint32_t tmem;
    asm volatile("ld.shared.b32 %0, [%1];" : "=r"(tmem) : "r"(sbase + OFF_TMEM));

    auto issue_stage = [&](int it) {
        int s = it % A_NSTAGE;
        int k0 = it * 32;
        uint32_t sb = sbase + OFF_BUF + s * A_STAGE_BYTES;
#pragma unroll
        for (int i = 0; i < 4; i++) {          // A: 256 rows x 4 kc-quads
            int idx = tid + i * 256;
            int row = idx >> 2;
            int kc = (idx & 3) * 8;
            uint32_t doff = SMEM_SWZ64((uint32_t)(row * 64 + kc * 2));
            CP_ASYNC16(sb + doff,         Ah + (size_t)(m0 + row) * NN + k0 + kc);
            CP_ASYNC16(sb + 16384 + doff, Al + (size_t)(m0 + row) * NN + k0 + kc);
        }
#pragma unroll
        for (int i = 0; i < 4; i++) {          // B: 256 rows x 4 kc-quads
            int idx = tid + i * 256;
            int row = idx >> 2;
            int kc = (idx & 3) * 8;
            uint32_t doff = SMEM_SWZ64((uint32_t)(row * 64 + kc * 2));
            CP_ASYNC16(sb + 32768 + doff, Bh + (size_t)row * NN + k0 + kc);
            CP_ASYNC16(sb + 49152 + doff, Bl + (size_t)row * NN + k0 + kc);
        }
    };

    const int NIT = NN / 32;   // 64
    issue_stage(0); CP_COMMIT();
    issue_stage(1); CP_COMMIT();

    int ph[A_NSTAGE] = {0, 0, 0};
    for (int it = 0; it < NIT; it++) {
        int s = it % A_NSTAGE;
        if (it + 1 < NIT) { CP_WAIT(1); } else { CP_WAIT(0); }
        // slot-free wait for stage it+2 (prior user: MMA batch it-1):
        // single elected thread waits; __syncthreads propagates to all.
        if (it >= 1 && it + 2 < NIT) {
            int so = (it - 1) % A_NSTAGE;
            if (wid == 0) {
                if (elect_one_pred()) {
                    MBARRIER_WAIT_PARITY(sbase + OFF_MBAR + so * 8, ph[so]);
                }
            }
            ph[so] ^= 1;   // all threads keep parity in sync
        }
        __syncthreads();
        if (wid == 0) {
            if (elect_one_pred()) {
                FENCE_PROXY_ASYNC();
                uint32_t sb = sbase + OFF_BUF + s * A_STAGE_BYTES;
#pragma unroll
                for (int hm = 0; hm < 2; hm++) {    // two M=128 halves, shared B
                    uint64_t dA[2] = { MAKE_DESC64(sb + hm * 8192),
                                       MAKE_DESC64(sb + 16384 + hm * 8192) };
                    uint64_t dB[2] = { MAKE_DESC64(sb + 32768),
                                       MAKE_DESC64(sb + 49152) };
                    uint32_t dacc = tmem + hm * 256;
#pragma unroll
                    for (int p = 0; p < 3; p++) {   // hi*hi, hi*lo, lo*hi
                        int ai = (p == 2) ? 1 : 0;
                        int bi2 = (p == 1) ? 1 : 0;
#pragma unroll
                        for (int ks = 0; ks < 2; ks++) {
                            uint32_t en = !(it == 0 && p == 0 && ks == 0);
                            mma_bf16_ss(dacc, dA[ai] + ks * 2, dB[bi2] + ks * 2,
                                        MMA_IDESC, en);
                        }
                    }
                }
                TCGEN05_COMMIT(sbase + OFF_MBAR + s * 8);
            }
        }
        if (it + 2 < NIT) issue_stage(it + 2);
        CP_COMMIT();
    }
    {
        // last commit (stage NIT-1) covers ALL prior MMAs by the issuing thread
        int sl = (NIT - 1) % A_NSTAGE;
        MBARRIER_WAIT_PARITY(sbase + OFF_MBAR + sl * 8, ph[sl]);
    }
    CP_WAIT(0);
    TCGEN05_FENCE_AFTER();
    __syncthreads();

    float* Ct = (float*)(smem + OFF_BUF);      // [128][264]  (16B-aligned rows)
    float* obase = out + (size_t)(n0g >> 8) * BATCH * NN * FF + (size_t)b * NN * FF;
#pragma unroll
    for (int hm = 0; hm < 2; hm++) {
        {
            int sp = wid & 3;
            int half = wid >> 2;
            int node = sp * 32 + lid;
#pragma unroll
            for (int c2 = 0; c2 < 4; c2++) {
                uint32_t dr[32];
                TCGEN05_LD_32X32B_X32(dr, tmem + hm * 256 + half * 128 + c2 * 32);
                TCGEN05_WAIT_LD();
                float* crow = Ct + node * CT_PAD + half * 128 + c2 * 32;
#pragma unroll
                for (int c = 0; c < 32; c += 4) {
                    float4 vv;
                    vv.x = __uint_as_float(dr[c + 0]);
                    vv.y = __uint_as_float(dr[c + 1]);
                    vv.z = __uint_as_float(dr[c + 2]);
                    vv.w = __uint_as_float(dr[c + 3]);
                    *(float4*)(crow + c) = vv;
                }
            }
            TCGEN05_FENCE_BEFORE();
        }
        __syncthreads();
        {
#pragma unroll 2
            for (int r = 0; r < 16; r++) {
                int m = wid * 16 + r;
                const float* crow = Ct + m * CT_PAD;
                float* orow = obase + (size_t)(m0 + hm * 128 + m) * FF;
#pragma unroll
                for (int hf = 0; hf < 2; hf++) {
                    float4 vv = *(const float4*)(crow + hf * 128 + lid * 4);
                    float4 o;
                    o.x = elu_f(vv.x); o.y = elu_f(vv.y);
                    o.z = elu_f(vv.z); o.w = elu_f(vv.w);
                    *(float4*)(orow + hf * 128 + lid * 4) = o;
                }
            }
        }
        __syncthreads();
    }

    if (tid == 0) {
        for (int i = 0; i < A_NSTAGE; i++) MBARRIER_INVAL(sbase + OFF_MBAR + i * 8);
    }
    __syncthreads();
    if (wid == 0) {
        TCGEN05_RELINQUISH();
        TCGEN05_DEALLOC(tmem, 512);
    }
#else
    // correct (slow) fallback — never runs when sm_103a SASS is present
    for (int e = tid; e < 256 * 256; e += 256) {
        int mi = e >> 8, nj = e & 255;
        float acc = 0.f;
        for (int k = 0; k < NN; k++) {
            float av = __bfloat162float(Ah[(size_t)(m0 + mi) * NN + k]) +
                       __bfloat162float(Al[(size_t)(m0 + mi) * NN + k]);
            float bv = __bfloat162float(Bh[(size_t)nj * NN + k]) +
                       __bfloat162float(Bl[(size_t)nj * NN + k]);
            acc += av * bv;
        }
        out[(size_t)(n0g >> 8) * BATCH * NN * FF + (size_t)b * NN * FF
            + (size_t)(m0 + mi) * FF + nj] = elu_f(acc);
    }
#endif
}

// ---------------------------------------------------------------------------
extern "C" void kernel_launch(void* const* d_in, const int* in_sizes, int n_in,
                              void* d_out, int out_size) {
    const float* h     = (const float*)d_in[0];
    const int*   adj   = (const int*)  d_in[1];
    const float* lrgt1 = (const float*)d_in[2];
    const float* W1    = (const float*)d_in[3];
    const float* W2    = (const float*)d_in[4];
    const float* a     = (const float*)d_in[5];
    float* out = (float*)d_out;

    __nv_bfloat16 *ath, *atl, *bth, *btl, *wth, *wtl;
    cudaGetSymbolAddress((void**)&ath, d_att_hi);
    cudaGetSymbolAddress((void**)&atl, d_att_lo);
    cudaGetSymbolAddress((void**)&bth, d_bth);
    cudaGetSymbolAddress((void**)&btl, d_btl);
    cudaGetSymbolAddress((void**)&wth, d_wth);
    cudaGetSymbolAddress((void**)&wtl, d_wtl);
    float* s1;  cudaGetSymbolAddress((void**)&s1,  d_s1);
    float* s2;  cudaGetSymbolAddress((void**)&s2,  d_s2);
    float* v;   cudaGetSymbolAddress((void**)&v,   d_v);

    v_kernel<<<1, 256>>>(W1, a, v);
    split_w<<<dim3(FF, 2), 256>>>(W1, W2, wth, wtl);

    cudaFuncSetAttribute(feat_mma, cudaFuncAttributeMaxDynamicSharedMemorySize, MMA_SMEM_BYTES);
    feat_mma<<<dim3(BN / 128, 2), 256, MMA_SMEM_BYTES>>>(h, lrgt1, wth, wtl, bth, btl);

    scores_kernel<<<BN / 8, 256>>>(h, v, s1, s2);
    softmax_kernel<<<BN, 256>>>(adj, s1, s2, ath, atl);

    cudaFuncSetAttribute(attn_mma, cudaFuncAttributeMaxDynamicSharedMemorySize, MMA_SMEM_BYTES);
    attn_mma<<<dim3(NN / 256, 2, BATCH), 256, MMA_SMEM_BYTES>>>(ath, atl, bth, btl, out);
}

// round 17
// speedup vs baseline: 1.0770x; 1.0770x over previous
#include <cuda_runtime.h>
#include <cuda_bf16.h>
#include <cstdint>
#include <math.h>

#define BATCH 8
#define NN 2048
#define FF 256
#define NFEAT 512              // Wh (256) stacked with wl (256)
#define BN (BATCH * NN)        // 16384
#define ALPHA 0.2f

// ---------------- scratch (static device allocations; no cudaMalloc) --------
__device__ __nv_bfloat16 d_att_hi[(size_t)BATCH * NN * NN];  // 67 MB
__device__ __nv_bfloat16 d_att_lo[(size_t)BATCH * NN * NN];  // 67 MB
__device__ __nv_bfloat16 d_bth[(size_t)BATCH * NFEAT * NN];  // 16 MB  [b][feat][node]
__device__ __nv_bfloat16 d_btl[(size_t)BATCH * NFEAT * NN];  // 16 MB
__device__ __nv_bfloat16 d_wth[2 * FF * FF];                 // W1^T|W2^T hi
__device__ __nv_bfloat16 d_wtl[2 * FF * FF];
__device__ float d_s1[BN];
__device__ float d_s2[BN];
__device__ float d_v[2 * FF];

// ---------------- kernel 1: v1 = W1 @ a[:F], v2 = W1 @ a[F:] ----------------
__global__ void v_kernel(const float* __restrict__ W1, const float* __restrict__ a,
                         float* __restrict__ v) {
    int k = threadIdx.x;
    float acc1 = 0.f, acc2 = 0.f;
    const float* wrow = W1 + (size_t)k * FF;
#pragma unroll 8
    for (int c = 0; c < FF; c++) {
        float w = wrow[c];
        acc1 += w * a[c];
        acc2 += w * a[FF + c];
    }
    v[k] = acc1;
    v[FF + k] = acc2;
}

// ------------- split helpers: fp32 -> bf16 hi/lo ----------------------------
__device__ __forceinline__ void split1(float p, __nv_bfloat16& hi, __nv_bfloat16& lo) {
    hi = __float2bfloat16(p);
    lo = __float2bfloat16(p - __bfloat162float(hi));
}

__global__ void split_w(const float* __restrict__ W1, const float* __restrict__ W2,
                        __nv_bfloat16* __restrict__ wth, __nv_bfloat16* __restrict__ wtl) {
    int z = blockIdx.y;
    int n = blockIdx.x;
    int k = threadIdx.x;
    const float* W = z ? W2 : W1;
    float p = W[(size_t)k * FF + n];     // transpose: Wt[n][k] = W[k][n]
    size_t o = (size_t)z * FF * FF + (size_t)n * FF + k;
    __nv_bfloat16 hi, lo;
    split1(p, hi, lo);
    wth[o] = hi;
    wtl[o] = lo;
}

// ------- kernel 3: s1 = h.v1, s2 = h.v2 (exact fp32, warp per row) ----------
__global__ void scores_kernel(const float* __restrict__ h, const float* __restrict__ v,
                              float* __restrict__ s1, float* __restrict__ s2) {
    int w = threadIdx.x >> 5, lane = threadIdx.x & 31;
    int r = blockIdx.x * 8 + w;
    const float4* hr = (const float4*)(h + (size_t)r * FF);
    const float4* v1p = (const float4*)v;
    const float4* v2p = (const float4*)(v + FF);
    float a1 = 0.f, a2 = 0.f;
#pragma unroll
    for (int i = 0; i < 2; i++) {
        int c4 = lane + i * 32;
        float4 hv = hr[c4];
        float4 x1 = v1p[c4];
        float4 x2 = v2p[c4];
        a1 += hv.x * x1.x + hv.y * x1.y + hv.z * x1.z + hv.w * x1.w;
        a2 += hv.x * x2.x + hv.y * x2.y + hv.z * x2.z + hv.w * x2.w;
    }
#pragma unroll
    for (int o = 16; o; o >>= 1) {
        a1 += __shfl_xor_sync(0xffffffffu, a1, o);
        a2 += __shfl_xor_sync(0xffffffffu, a2, o);
    }
    if (lane == 0) { s1[r] = a1; s2[r] = a2; }
}

// --- kernel 4: masked leaky-relu softmax (register-resident) -> bf16 hi/lo --
__global__ void softmax_kernel(const int* __restrict__ adj, const float* __restrict__ s1,
                               const float* __restrict__ s2,
                               __nv_bfloat16* __restrict__ att_hi,
                               __nv_bfloat16* __restrict__ att_lo) {
    int bi = blockIdx.x;
    int b = bi >> 11;
    const int4* arow = (const int4*)(adj + (size_t)bi * NN);
    const float4* s2b = (const float4*)(s2 + (size_t)b * NN);
    float si = s1[bi];

    __shared__ float redm[8];
    __shared__ float reds[8];
    int tid = threadIdx.x;
    int lane = tid & 31, warp = tid >> 5;

    float r[8];
    float lmax = -3.4e38f;
#pragma unroll
    for (int c = 0; c < 2; c++) {
        int j4 = tid + c * 256;
        int4 av = arow[j4];
        float4 sv = s2b[j4];
        float v0 = si + sv.x; v0 = v0 > 0.f ? v0 : ALPHA * v0; v0 = av.x > 0 ? v0 : -9.0e15f;
        float v1 = si + sv.y; v1 = v1 > 0.f ? v1 : ALPHA * v1; v1 = av.y > 0 ? v1 : -9.0e15f;
        float v2 = si + sv.z; v2 = v2 > 0.f ? v2 : ALPHA * v2; v2 = av.z > 0 ? v2 : -9.0e15f;
        float v3 = si + sv.w; v3 = v3 > 0.f ? v3 : ALPHA * v3; v3 = av.w > 0 ? v3 : -9.0e15f;
        r[c * 4 + 0] = v0; r[c * 4 + 1] = v1; r[c * 4 + 2] = v2; r[c * 4 + 3] = v3;
        lmax = fmaxf(fmaxf(fmaxf(lmax, v0), fmaxf(v1, v2)), v3);
    }
#pragma unroll
    for (int o = 16; o; o >>= 1) lmax = fmaxf(lmax, __shfl_xor_sync(0xffffffffu, lmax, o));
    if (lane == 0) redm[warp] = lmax;
    __syncthreads();
    float m = redm[0];
#pragma unroll
    for (int w = 1; w < 8; w++) m = fmaxf(m, redm[w]);

    float lsum = 0.f;
#pragma unroll
    for (int q = 0; q < 8; q++) {
        float e = __expf(r[q] - m);
        r[q] = e;
        lsum += e;
    }
#pragma unroll
    for (int o = 16; o; o >>= 1) lsum += __shfl_xor_sync(0xffffffffu, lsum, o);
    if (lane == 0) reds[warp] = lsum;
    __syncthreads();
    float tot = 0.f;
#pragma unroll
    for (int w = 0; w < 8; w++) tot += reds[w];
    float inv = 1.f / tot;

    uint2* oh = (uint2*)(att_hi + (size_t)bi * NN);
    uint2* ol = (uint2*)(att_lo + (size_t)bi * NN);
#pragma unroll
    for (int c = 0; c < 2; c++) {
        int j4 = tid + c * 256;
        union { __nv_bfloat16 h[4]; uint2 u; } H, L;
#pragma unroll
        for (int q = 0; q < 4; q++) {
            float p = r[c * 4 + q] * inv;
            H.h[q] = __float2bfloat16(p);
            L.h[q] = __float2bfloat16(p - __bfloat162float(H.h[q]));
        }
        oh[j4] = H.u;
        ol[j4] = L.u;
    }
}

// ======================= shared helpers =====================================
__device__ __forceinline__ uint32_t smem_u32(const void* p) {
    uint32_t a;
    asm("{ .reg .u64 t; cvta.to.shared.u64 t, %1; cvt.u32.u64 %0, t; }"
        : "=r"(a) : "l"(p));
    return a;
}
__device__ __forceinline__ float elu_f(float v) {
    return v > 0.f ? v : (__expf(v) - 1.f);
}

#define OFF_TMEM 0
#define OFF_MBAR 8
#define OFF_BUF  1024
// feat_mma: 4 stages x 48KB (K-tile 32)
#define F_STAGE_BYTES 49152
#define F_NSTAGE 4
// attn_mma: 3 stages x 64KB (M=256: Ahi 16K | Alo 16K | Bhi 16K | Blo 16K)
#define A_STAGE_BYTES 65536
#define A_NSTAGE 3
#define MMA_SMEM_BYTES (OFF_BUF + 3 * A_STAGE_BYTES)      // 197632 (covers both)
#define CT_PAD 264                     // floats; 264*4=1056 bytes, 16B-aligned rows

#if defined(__CUDA_ARCH__) && (defined(__CUDA_ARCH_FEAT_SM103_ALL) || defined(__CUDA_ARCH_FEAT_SM100_ALL) || defined(__CUDA_ARCH_FEAT_SM101_ALL))
#define HAS_TCGEN05 1
#else
#define HAS_TCGEN05 0
#endif

#if HAS_TCGEN05
// ================= tcgen05 helpers (sm_103a SASS) ===========================
__device__ __forceinline__ uint32_t elect_one_pred() {
    uint32_t pred;
    asm volatile(
        "{\n\t.reg .pred p;\n\telect.sync _|p, 0xFFFFFFFF;\n\t"
        "selp.b32 %0, 1, 0, p;\n\t}" : "=r"(pred));
    return pred;
}
#define MBARRIER_INIT(addr, cnt) \
    asm volatile("mbarrier.init.shared.b64 [%0], %1;" :: "r"((uint32_t)(addr)), "r"((uint32_t)(cnt)) : "memory")
#define MBARRIER_INVAL(addr) \
    asm volatile("mbarrier.inval.shared.b64 [%0];" :: "r"((uint32_t)(addr)) : "memory")
#define MBARRIER_WAIT_PARITY(mbar_smem_addr, phase_parity) do { \
    uint32_t _mbar = (uint32_t)(mbar_smem_addr); \
    uint32_t _parity = (uint32_t)(phase_parity); \
    uint32_t _done; \
    asm volatile( \
        "{\n\t.reg .pred p;\n\t" \
        "mbarrier.try_wait.parity.acquire.cta.shared::cta.b64 p, [%1], %2;\n\t" \
        "selp.b32 %0, 1, 0, p;\n\t}" \
        : "=r"(_done) : "r"(_mbar), "r"(_parity) : "memory"); \
    if (!_done) { \
        asm volatile( \
            "{\n\t.reg .pred P1;\n\t" \
            "WAIT_LOOP_%=:\n\t" \
            "mbarrier.try_wait.parity.acquire.cta.shared::cta.b64 P1, [%0], %1, 0x989680;\n\t" \
            "@P1 bra.uni WAIT_DONE_%=;\n\t" \
            "bra.uni WAIT_LOOP_%=;\n\t" \
            "WAIT_DONE_%=:\n\t}" \
            :: "r"(_mbar), "r"(_parity) : "memory"); \
    } \
} while (0)
#define TCGEN05_ALLOC(saddr, n) \
    asm volatile("tcgen05.alloc.cta_group::1.sync.aligned.shared::cta.b32 [%0], %1;" \
                 :: "r"((uint32_t)(saddr)), "r"((uint32_t)(n)) : "memory")
#define TCGEN05_DEALLOC(tm, n) \
    asm volatile("tcgen05.dealloc.cta_group::1.sync.aligned.b32 %0, %1;" :: "r"(tm), "r"((uint32_t)(n)))
#define TCGEN05_RELINQUISH() \
    asm volatile("tcgen05.relinquish_alloc_permit.cta_group::1.sync.aligned;")
#define TCGEN05_COMMIT(mbar) \
    asm volatile("tcgen05.commit.cta_group::1.mbarrier::arrive::one.shared::cluster.b64 [%0];" \
                 :: "r"((uint32_t)(mbar)) : "memory")
#define TCGEN05_FENCE_AFTER() asm volatile("tcgen05.fence::after_thread_sync;" ::: "memory")
#define TCGEN05_FENCE_BEFORE() asm volatile("tcgen05.fence::before_thread_sync;" ::: "memory")
#define TCGEN05_WAIT_LD() asm volatile("tcgen05.wait::ld.sync.aligned;" ::: "memory")
#define FENCE_PROXY_ASYNC() asm volatile("fence.proxy.async.shared::cta;" ::: "memory")
#define CP_ASYNC16(dst, src) \
    asm volatile("cp.async.cg.shared.global [%0], [%1], 16;" :: "r"((uint32_t)(dst)), "l"(src) : "memory")
#define CP_COMMIT() asm volatile("cp.async.commit_group;" ::: "memory")
#define CP_WAIT(n)  asm volatile("cp.async.wait_group %0;" :: "n"(n) : "memory")
#define TCGEN05_LD_32X32B_X32(r, tmem_addr) \
    asm volatile( \
        "tcgen05.ld.sync.aligned.32x32b.x32.b32 " \
        "{%0, %1, %2, %3, %4, %5, %6, %7, " \
        " %8, %9, %10, %11, %12, %13, %14, %15, " \
        " %16, %17, %18, %19, %20, %21, %22, %23, " \
        " %24, %25, %26, %27, %28, %29, %30, %31}, [%32];" \
        : "=r"((r)[0]),  "=r"((r)[1]),  "=r"((r)[2]),  "=r"((r)[3]), \
          "=r"((r)[4]),  "=r"((r)[5]),  "=r"((r)[6]),  "=r"((r)[7]), \
          "=r"((r)[8]),  "=r"((r)[9]),  "=r"((r)[10]), "=r"((r)[11]), \
          "=r"((r)[12]), "=r"((r)[13]), "=r"((r)[14]), "=r"((r)[15]), \
          "=r"((r)[16]), "=r"((r)[17]), "=r"((r)[18]), "=r"((r)[19]), \
          "=r"((r)[20]), "=r"((r)[21]), "=r"((r)[22]), "=r"((r)[23]), \
          "=r"((r)[24]), "=r"((r)[25]), "=r"((r)[26]), "=r"((r)[27]), \
          "=r"((r)[28]), "=r"((r)[29]), "=r"((r)[30]), "=r"((r)[31]) \
        : "r"(tmem_addr))

// SW64 K-major descriptor: layout=4, version=1, SBO=32 (512B = 8 rows x 64B), LBO=1
static constexpr uint64_t SMEM_DESC_BASE_SW64 =
    (uint64_t(4) << 61) | (uint64_t(1) << 46) | (uint64_t(32) << 32) | (uint64_t(1) << 16);
#define MAKE_DESC64(base_addr) \
    (SMEM_DESC_BASE_SW64 | ((uint64_t)((base_addr) >> 4) & 0x3FFF))
#define SMEM_SWZ64(o) ((o) ^ (((o) >> 3) & 0x30))

__device__ __forceinline__ void mma_bf16_ss(uint32_t d_tmem, uint64_t a_desc,
                                            uint64_t b_desc, uint32_t idesc, uint32_t en) {
    asm volatile(
        "{\n\t.reg .pred p;\n\tsetp.ne.u32 p, %4, 0;\n\t"
        "tcgen05.mma.cta_group::1.kind::f16 [%0], %1, %2, %3, {%5, %5, %5, %5}, p;\n\t}"
        :: "r"(d_tmem), "l"(a_desc), "l"(b_desc), "r"(idesc), "r"(en), "r"(0u)
        : "memory");
}
// idesc: f32 accum, bf16 a/b, N=256, M=128
static constexpr uint32_t MMA_IDESC =
    (1u << 4) | (1u << 7) | (1u << 10) | ((256u / 8) << 17) | ((128u / 16) << 24);
#endif  // HAS_TCGEN05

// ============ kernel 2: feat_mma: BT[hi/lo] = split((x @ W)^T) ==============
// M=128 nodes, N=256 feats, K=256; 4-stage K32. A fp32->bf16 split in-kernel.
__global__ void __launch_bounds__(256, 1)
feat_mma(const float* __restrict__ xh_f32 /*h*/, const float* __restrict__ lr_f32,
         const __nv_bfloat16* __restrict__ wth, const __nv_bfloat16* __restrict__ wtl,
         __nv_bfloat16* __restrict__ BTh, __nv_bfloat16* __restrict__ BTl) {
    extern __shared__ char smem[];
    const int tid = threadIdx.x;
    const int wid = tid >> 5;
    const int lid = tid & 31;
    const int m0 = blockIdx.x * 128;
    const int z = blockIdx.y;
    const float* A = (z ? lr_f32 : xh_f32) + (size_t)m0 * FF;
    const __nv_bfloat16* Bh = wth + (size_t)z * FF * FF;
    const __nv_bfloat16* Bl = wtl + (size_t)z * FF * FF;
    const int b = m0 >> 11;
    const int node0 = m0 & (NN - 1);

#if HAS_TCGEN05
    uint32_t sbase = smem_u32(smem);
    if (wid == 0) TCGEN05_ALLOC(sbase + OFF_TMEM, 256);
    if (tid == 0) {
        for (int i = 0; i < F_NSTAGE; i++) MBARRIER_INIT(sbase + OFF_MBAR + i * 8, 1);
    }
    __syncthreads();
    uint32_t tmem;
    asm volatile("ld.shared.b32 %0, [%1];" : "=r"(tmem) : "r"(sbase + OFF_TMEM));

    const int arow0 = tid >> 2;
    const int akc = (tid & 3) * 8;

    auto lda = [&](int it, float4* rg) {
        int k0 = it * 32;
#pragma unroll
        for (int i = 0; i < 2; i++) {
            int row = arow0 + i * 64;
            const float* p = A + (size_t)row * FF + k0 + akc;
            rg[i * 2 + 0] = *(const float4*)p;
            rg[i * 2 + 1] = *(const float4*)(p + 4);
        }
    };
    auto sta = [&](int it, const float4* rg) {
        int s = it & (F_NSTAGE - 1);
        char* sb = smem + OFF_BUF + s * F_STAGE_BYTES;
#pragma unroll
        for (int i = 0; i < 2; i++) {
            int row = arow0 + i * 64;
            uint32_t doff = SMEM_SWZ64((uint32_t)(row * 64 + akc * 2));
            union { __nv_bfloat16 h[8]; uint4 u; } H, L;
            const float* f = (const float*)&rg[i * 2];
#pragma unroll
            for (int q = 0; q < 8; q++) split1(f[q], H.h[q], L.h[q]);
            *(uint4*)(sb + doff) = H.u;
            *(uint4*)(sb + 8192 + doff) = L.u;
        }
    };
    auto ldb = [&](int it) {
        int s = it & (F_NSTAGE - 1);
        int k0 = it * 32;
        uint32_t sb = sbase + OFF_BUF + s * F_STAGE_BYTES;
#pragma unroll
        for (int i = 0; i < 4; i++) {
            int idx = tid + i * 256;
            int row = idx >> 2;
            int kc = (idx & 3) * 8;
            uint32_t doff = SMEM_SWZ64((uint32_t)(row * 64 + kc * 2));
            CP_ASYNC16(sb + 16384 + doff, Bh + (size_t)row * FF + k0 + kc);
            CP_ASYNC16(sb + 32768 + doff, Bl + (size_t)row * FF + k0 + kc);
        }
    };

    const int NIT = FF / 32;   // 8
    {
        float4 r0[4], r1[4], r2[4];
        lda(0, r0); lda(1, r1); lda(2, r2);
        sta(0, r0); ldb(0); CP_COMMIT();
        sta(1, r1); ldb(1); CP_COMMIT();
        sta(2, r2); ldb(2); CP_COMMIT();
    }

    float4 rg[4];
    int ph[F_NSTAGE] = {0, 0, 0, 0};
    for (int it = 0; it < NIT; it++) {
        int s = it & (F_NSTAGE - 1);
        if (it + 3 < NIT) lda(it + 3, rg);
        CP_WAIT(2);
        __syncthreads();
        if (wid == 0) {
            FENCE_PROXY_ASYNC();
            if (elect_one_pred()) {
                uint32_t sb = sbase + OFF_BUF + s * F_STAGE_BYTES;
                uint64_t dA[2] = { MAKE_DESC64(sb),         MAKE_DESC64(sb + 8192) };
                uint64_t dB[2] = { MAKE_DESC64(sb + 16384), MAKE_DESC64(sb + 32768) };
#pragma unroll
                for (int p = 0; p < 3; p++) {
                    int ai = (p == 2) ? 1 : 0;
                    int bi2 = (p == 1) ? 1 : 0;
#pragma unroll
                    for (int ks = 0; ks < 2; ks++) {
                        uint32_t en = !(it == 0 && p == 0 && ks == 0);
                        mma_bf16_ss(tmem, dA[ai] + ks * 2, dB[bi2] + ks * 2, MMA_IDESC, en);
                    }
                }
                TCGEN05_COMMIT(sbase + OFF_MBAR + s * 8);
            }
        }
        if (it + 3 < NIT) {
            if (it >= 1) {
                int so = (it - 1) & (F_NSTAGE - 1);
                MBARRIER_WAIT_PARITY(sbase + OFF_MBAR + so * 8, ph[so]);
                ph[so] ^= 1;
            }
            sta(it + 3, rg);
            ldb(it + 3);
        }
        CP_COMMIT();
    }
    {
        int sl = (NIT - 1) & (F_NSTAGE - 1);
        MBARRIER_WAIT_PARITY(sbase + OFF_MBAR + sl * 8, ph[sl]);
    }
    CP_WAIT(0);
    TCGEN05_FENCE_AFTER();
    __syncthreads();

    float* Ct = (float*)(smem + OFF_BUF);      // [256][128]
    {
        int sp = wid & 3;
        int half = wid >> 2;
        int node = sp * 32 + lid;
#pragma unroll
        for (int c2 = 0; c2 < 4; c2++) {
            uint32_t dr[32];
            TCGEN05_LD_32X32B_X32(dr, tmem + half * 128 + c2 * 32);
            TCGEN05_WAIT_LD();
            int f0 = half * 128 + c2 * 32;
#pragma unroll
            for (int c = 0; c < 32; c++)
                Ct[(f0 + c) * 128 + node] = __uint_as_float(dr[c]);
        }
        TCGEN05_FENCE_BEFORE();
    }
    __syncthreads();
    {
#pragma unroll 4
        for (int j = 0; j < 32; j++) {
            int f = wid * 32 + j;
            float4 vv = *(const float4*)(Ct + f * 128 + lid * 4);
            union { __nv_bfloat16 h[4]; uint2 u; } H, L;
            split1(vv.x, H.h[0], L.h[0]);
            split1(vv.y, H.h[1], L.h[1]);
            split1(vv.z, H.h[2], L.h[2]);
            split1(vv.w, H.h[3], L.h[3]);
            size_t rowbase = ((size_t)b * NFEAT + z * 256 + f) * NN + node0 + lid * 4;
            *(uint2*)(BTh + rowbase) = H.u;
            *(uint2*)(BTl + rowbase) = L.u;
        }
    }
    __syncthreads();
    if (tid == 0) {
        for (int i = 0; i < F_NSTAGE; i++) MBARRIER_INVAL(sbase + OFF_MBAR + i * 8);
    }
    __syncthreads();
    if (wid == 0) {
        TCGEN05_RELINQUISH();
        TCGEN05_DEALLOC(tmem, 256);
    }
#else
    for (int e = tid; e < 128 * 256; e += 256) {
        int mi = e >> 8, nj = e & 255;
        float acc = 0.f;
        for (int k = 0; k < FF; k++) {
            float av = A[(size_t)mi * FF + k];
            float bv = __bfloat162float(Bh[(size_t)nj * FF + k]) +
                       __bfloat162float(Bl[(size_t)nj * FF + k]);
            acc += av * bv;
        }
        __nv_bfloat16 hi, lo;
        split1(acc, hi, lo);
        size_t o = ((size_t)b * NFEAT + z * 256 + nj) * NN + node0 + mi;
        BTh[o] = hi;
        BTl[o] = lo;
    }
#endif
}

// ============== kernel 5: attn_mma: out = elu(att @ [Wh|wl]) ================
// M=256 per CTA (two 128-row TMEM accumulators sharing one B tile), N=256.
// K=2048 in 64 tiles of 32; 3-stage x 64KB synchronous pipeline.
__global__ void __launch_bounds__(256, 1)
attn_mma(const __nv_bfloat16* __restrict__ att_hi, const __nv_bfloat16* __restrict__ att_lo,
         const __nv_bfloat16* __restrict__ BTh, const __nv_bfloat16* __restrict__ BTl,
         float* __restrict__ out) {
    extern __shared__ char smem[];
    const int tid = threadIdx.x;
    const int wid = tid >> 5;
    const int lid = tid & 31;
    const int b = blockIdx.z;
    const int m0 = blockIdx.x * 256;
    const int n0g = blockIdx.y * 256;     // 0 -> out1, 256 -> out2
    const __nv_bfloat16* Ah = att_hi + (size_t)b * NN * NN;
    const __nv_bfloat16* Al = att_lo + (size_t)b * NN * NN;
    const __nv_bfloat16* Bh = BTh + (size_t)b * NFEAT * NN + (size_t)n0g * NN;
    const __nv_bfloat16* Bl = BTl + (size_t)b * NFEAT * NN + (size_t)n0g * NN;

#if HAS_TCGEN05
    uint32_t sbase = smem_u32(smem);
    if (wid == 0) TCGEN05_ALLOC(sbase + OFF_TMEM, 512);
    if (tid == 0) {
        for (int i = 0; i < A_NSTAGE; i++) MBARRIER_INIT(sbase + OFF_MBAR + i * 8, 1);
    }
    __syncthreads();
    uint32_t tmem;
    asm volatile("ld.shared.b32 %0, [%1];" : "=r"(tmem) : "r"(sbase + OFF_TMEM));

    auto issue_stage = [&](int it) {
        int s = it % A_NSTAGE;
        int k0 = it * 32;
        uint32_t sb = sbase + OFF_BUF + s * A_STAGE_BYTES;
#pragma unroll
        for (int i = 0; i < 4; i++) {          // A: 256 rows x 4 kc-quads
            int idx = tid + i * 256;
            int row = idx >> 2;
            int kc = (idx & 3) * 8;
            uint32_t doff = SMEM_SWZ64((uint32_t)(row * 64 + kc * 2));
            CP_ASYNC16(sb + doff,         Ah + (size_t)(m0 + row) * NN + k0 + kc);
            CP_ASYNC16(sb + 16384 + doff, Al + (size_t)(m0 + row) * NN + k0 + kc);
        }
#pragma unroll
        for (int i = 0; i < 4; i++) {          // B: 256 rows x 4 kc-quads
            int idx = tid + i * 256;
            int row = idx >> 2;
            int kc = (idx & 3) * 8;
            uint32_t doff = SMEM_SWZ64((uint32_t)(row * 64 + kc * 2));
            CP_ASYNC16(sb + 32768 + doff, Bh + (size_t)row * NN + k0 + kc);
            CP_ASYNC16(sb + 49152 + doff, Bl + (size_t)row * NN + k0 + kc);
        }
    };

    const int NIT = NN / 32;   // 64
    issue_stage(0); CP_COMMIT();
    issue_stage(1); CP_COMMIT();

    int ph[A_NSTAGE] = {0, 0, 0};
    for (int it = 0; it < NIT; it++) {
        int s = it % A_NSTAGE;
        if (it + 1 < NIT) { CP_WAIT(1); } else { CP_WAIT(0); }
        __syncthreads();
        if (wid == 0) {
            FENCE_PROXY_ASYNC();
            if (elect_one_pred()) {
                uint32_t sb = sbase + OFF_BUF + s * A_STAGE_BYTES;
#pragma unroll
                for (int hm = 0; hm < 2; hm++) {    // two M=128 halves, shared B
                    uint64_t dA[2] = { MAKE_DESC64(sb + hm * 8192),
                                       MAKE_DESC64(sb + 16384 + hm * 8192) };
                    uint64_t dB[2] = { MAKE_DESC64(sb + 32768),
                                       MAKE_DESC64(sb + 49152) };
                    uint32_t dacc = tmem + hm * 256;
#pragma unroll
                    for (int p = 0; p < 3; p++) {   // hi*hi, hi*lo, lo*hi
                        int ai = (p == 2) ? 1 : 0;
                        int bi2 = (p == 1) ? 1 : 0;
#pragma unroll
                        for (int ks = 0; ks < 2; ks++) {
                            uint32_t en = !(it == 0 && p == 0 && ks == 0);
                            mma_bf16_ss(dacc, dA[ai] + ks * 2, dB[bi2] + ks * 2,
                                        MMA_IDESC, en);
                        }
                    }
                }
                TCGEN05_COMMIT(sbase + OFF_MBAR + s * 8);
            }
        }
        if (it + 2 < NIT) {
            if (it >= 1) {
                int so = (it - 1) % A_NSTAGE;
                MBARRIER_WAIT_PARITY(sbase + OFF_MBAR + so * 8, ph[so]);
                ph[so] ^= 1;
            }
            issue_stage(it + 2);
        }
        CP_COMMIT();
    }
    {
        // last commit (stage NIT-1) covers ALL prior MMAs by the issuing thread
        int sl = (NIT - 1) % A_NSTAGE;
        MBARRIER_WAIT_PARITY(sbase + OFF_MBAR + sl * 8, ph[sl]);
    }
    CP_WAIT(0);
    TCGEN05_FENCE_AFTER();
    __syncthreads();

    float* Ct = (float*)(smem + OFF_BUF);      // [128][264]  (16B-aligned rows)
    float* obase = out + (size_t)(n0g >> 8) * BATCH * NN * FF + (size_t)b * NN * FF;
#pragma unroll
    for (int hm = 0; hm < 2; hm++) {
        {
            int sp = wid & 3;
            int half = wid >> 2;
            int node = sp * 32 + lid;
#pragma unroll
            for (int c2 = 0; c2 < 4; c2++) {
                uint32_t dr[32];
                TCGEN05_LD_32X32B_X32(dr, tmem + hm * 256 + half * 128 + c2 * 32);
                TCGEN05_WAIT_LD();
                float* crow = Ct + node * CT_PAD + half * 128 + c2 * 32;
#pragma unroll
                for (int c = 0; c < 32; c += 4) {
                    float4 vv;
                    vv.x = __uint_as_float(dr[c + 0]);
                    vv.y = __uint_as_float(dr[c + 1]);
                    vv.z = __uint_as_float(dr[c + 2]);
                    vv.w = __uint_as_float(dr[c + 3]);
                    *(float4*)(crow + c) = vv;
                }
            }
            TCGEN05_FENCE_BEFORE();
        }
        __syncthreads();
        {
#pragma unroll 2
            for (int r = 0; r < 16; r++) {
                int m = wid * 16 + r;
                const float* crow = Ct + m * CT_PAD;
                float* orow = obase + (size_t)(m0 + hm * 128 + m) * FF;
#pragma unroll
                for (int hf = 0; hf < 2; hf++) {
                    float4 vv = *(const float4*)(crow + hf * 128 + lid * 4);
                    float4 o;
                    o.x = elu_f(vv.x); o.y = elu_f(vv.y);
                    o.z = elu_f(vv.z); o.w = elu_f(vv.w);
                    *(float4*)(orow + hf * 128 + lid * 4) = o;
                }
            }
        }
        __syncthreads();
    }

    if (tid == 0) {
        for (int i = 0; i < A_NSTAGE; i++) MBARRIER_INVAL(sbase + OFF_MBAR + i * 8);
    }
    __syncthreads();
    if (wid == 0) {
        TCGEN05_RELINQUISH();
        TCGEN05_DEALLOC(tmem, 512);
    }
#else
    // correct (slow) fallback — never runs when sm_103a SASS is present
    for (int e = tid; e < 256 * 256; e += 256) {
        int mi = e >> 8, nj = e & 255;
        float acc = 0.f;
        for (int k = 0; k < NN; k++) {
            float av = __bfloat162float(Ah[(size_t)(m0 + mi) * NN + k]) +
                       __bfloat162float(Al[(size_t)(m0 + mi) * NN + k]);
            float bv = __bfloat162float(Bh[(size_t)nj * NN + k]) +
                       __bfloat162float(Bl[(size_t)nj * NN + k]);
            acc += av * bv;
        }
        out[(size_t)(n0g >> 8) * BATCH * NN * FF + (size_t)b * NN * FF
            + (size_t)(m0 + mi) * FF + nj] = elu_f(acc);
    }
#endif
}

// ---------------------------------------------------------------------------
extern "C" void kernel_launch(void* const* d_in, const int* in_sizes, int n_in,
                              void* d_out, int out_size) {
    const float* h     = (const float*)d_in[0];
    const int*   adj   = (const int*)  d_in[1];
    const float* lrgt1 = (const float*)d_in[2];
    const float* W1    = (const float*)d_in[3];
    const float* W2    = (const float*)d_in[4];
    const float* a     = (const float*)d_in[5];
    float* out = (float*)d_out;

    __nv_bfloat16 *ath, *atl, *bth, *btl, *wth, *wtl;
    cudaGetSymbolAddress((void**)&ath, d_att_hi);
    cudaGetSymbolAddress((void**)&atl, d_att_lo);
    cudaGetSymbolAddress((void**)&bth, d_bth);
    cudaGetSymbolAddress((void**)&btl, d_btl);
    cudaGetSymbolAddress((void**)&wth, d_wth);
    cudaGetSymbolAddress((void**)&wtl, d_wtl);
    float* s1;  cudaGetSymbolAddress((void**)&s1,  d_s1);
    float* s2;  cudaGetSymbolAddress((void**)&s2,  d_s2);
    float* v;   cudaGetSymbolAddress((void**)&v,   d_v);

    cudaFuncSetAttribute(feat_mma, cudaFuncAttributeMaxDynamicSharedMemorySize, MMA_SMEM_BYTES);
    cudaFuncSetAttribute(attn_mma, cudaFuncAttributeMaxDynamicSharedMemorySize, MMA_SMEM_BYTES);

    // Fork a second stream so the weight/feature chain (split_w -> feat_mma,
    // tensor-bound) overlaps the logits chain (v -> scores -> softmax,
    // DRAM-bound). Event fork/join keeps this graph-capturable.
    cudaStream_t sB;
    cudaEvent_t evFork, evJoin;
    cudaStreamCreateWithFlags(&sB, cudaStreamNonBlocking);
    cudaEventCreateWithFlags(&evFork, cudaEventDisableTiming);
    cudaEventCreateWithFlags(&evJoin, cudaEventDisableTiming);

    cudaEventRecord(evFork, 0);
    cudaStreamWaitEvent(sB, evFork, 0);

    // stream B: weights + feature GEMM
    split_w<<<dim3(FF, 2), 256, 0, sB>>>(W1, W2, wth, wtl);
    feat_mma<<<dim3(BN / 128, 2), 256, MMA_SMEM_BYTES, sB>>>(h, lrgt1, wth, wtl, bth, btl);
    cudaEventRecord(evJoin, sB);

    // default stream: logits chain
    v_kernel<<<1, 256>>>(W1, a, v);
    scores_kernel<<<BN / 8, 256>>>(h, v, s1, s2);
    softmax_kernel<<<BN, 256>>>(adj, s1, s2, ath, atl);

    // join, then the big GEMM
    cudaStreamWaitEvent(0, evJoin, 0);
    attn_mma<<<dim3(NN / 256, 2, BATCH), 256, MMA_SMEM_BYTES>>>(ath, atl, bth, btl, out);

    cudaEventDestroy(evFork);
    cudaEventDestroy(evJoin);
    cudaStreamDestroy(sB);
}